// round 3
// baseline (speedup 1.0000x reference)
#include <cuda_runtime.h>
#include <math.h>

// Shapes (fixed by the problem; V derived from in_sizes at launch)
#define H 1024
#define E 1024
#define L 2048
#define HE 2048          // H + E
#define H3 3072          // 3*H
#define ECHUNKS 16
#define ECHUNK  (E / ECHUNKS)   // 64

// ---------------- scratch (__device__ globals; no allocation) ----------------
__device__ __align__(16) float g_d[E];
__device__ __align__(16) float g_x[HE];              // concat(g, c)
__device__ __align__(16) float g_part[ECHUNKS * L];
__device__ __align__(16) float g_attn[L];
__device__ __align__(16) float g_gx[H3];
__device__ __align__(16) float g_gh[H3];
__device__ __align__(16) float g_hnew[H];
__device__ float g_sum;                              // sum of exp(logits)

// ---------------- helpers ----------------
__device__ __forceinline__ float warp_sum(float v) {
    #pragma unroll
    for (int o = 16; o; o >>= 1) v += __shfl_down_sync(0xffffffffu, v, o);
    return v;
}
__device__ __forceinline__ float warp_max(float v) {
    #pragma unroll
    for (int o = 16; o; o >>= 1) v = fmaxf(v, __shfl_down_sync(0xffffffffu, v, o));
    return v;
}
__device__ __forceinline__ float dot4(const float4 a, const float4 b) {
    return a.x * b.x + a.y * b.y + a.z * b.z + a.w * b.w;
}
__device__ __forceinline__ float sigmoidf(float x) { return 1.0f / (1.0f + expf(-x)); }

// warp-cooperative dot over 1024 floats: 8 batched LDG.128 per operand.
__device__ __forceinline__ float wdot1024(const float* __restrict__ row,
                                          const float* __restrict__ vec, int lane) {
    const float4* r4 = reinterpret_cast<const float4*>(row);
    const float4* v4 = reinterpret_cast<const float4*>(vec);
    float4 w[8], x[8];
    #pragma unroll
    for (int k = 0; k < 8; k++) w[k] = r4[lane + 32 * k];
    #pragma unroll
    for (int k = 0; k < 8; k++) x[k] = v4[lane + 32 * k];
    float a0 = 0.f, a1 = 0.f;
    #pragma unroll
    for (int k = 0; k < 8; k += 2) { a0 += dot4(w[k], x[k]); a1 += dot4(w[k+1], x[k+1]); }
    return a0 + a1;  // caller warp-reduces
}
// warp-cooperative dot over 2048 floats: two 8-deep batches.
__device__ __forceinline__ float wdot2048(const float* __restrict__ row,
                                          const float* __restrict__ vec, int lane) {
    float a = wdot1024(row, vec, lane);
    float b = wdot1024(row + 1024, vec + 1024, lane);
    return a + b;
}

// ======== k1: warp-per-row. rows [0,E): d[e]; rows [E, E+H3): gh[r] ========
__global__ __launch_bounds__(256) void k1_dvec_gh(
        const int* __restrict__ y, const float* __restrict__ h,
        const float* __restrict__ emb, const float* __restrict__ W_t,
        const float* __restrict__ b_t,
        const float* __restrict__ W_hh, const float* __restrict__ b_hh) {
    int r    = (blockIdx.x * blockDim.x + threadIdx.x) >> 5;
    int lane = threadIdx.x & 31;
    if (r < E) {
        float acc = warp_sum(wdot1024(W_t + (size_t)r * H, h, lane));
        if (lane == 0) {
            float g = emb[(size_t)y[0] * H + r];
            g_d[r] = acc + b_t[r] + g;
            g_x[r] = g;
        }
    } else if (r < E + H3) {
        int j = r - E;
        float acc = warp_sum(wdot1024(W_hh + (size_t)j * H, h, lane));
        if (lane == 0) g_gh[j] = acc + b_hh[j];
    }
}

// ======== k2: partial scores over E-chunks (coalesced over l) ========
__global__ __launch_bounds__(256) void k2_scores(const float* __restrict__ cnn_a) {
    __shared__ float ds[ECHUNK];
    int l  = blockIdx.x * blockDim.x + threadIdx.x;
    int e0 = blockIdx.y * ECHUNK;
    if (threadIdx.x < ECHUNK) ds[threadIdx.x] = g_d[e0 + threadIdx.x];
    __syncthreads();
    const float* __restrict__ col = cnn_a + (size_t)e0 * L + l;
    float a0 = 0.f, a1 = 0.f;
    #pragma unroll
    for (int e = 0; e < ECHUNK; e += 2) {
        a0 += ds[e]     * col[(size_t)e * L];
        a1 += ds[e + 1] * col[(size_t)(e + 1) * L];
    }
    g_part[blockIdx.y * L + l] = a0 + a1;
}

// ======== k3: softmax over L (single block, 1024 threads) ========
__global__ __launch_bounds__(1024) void k3_softmax() {
    __shared__ float red[32];
    __shared__ float bval;
    int t = threadIdx.x;
    float s0 = 0.f, s1 = 0.f;
    #pragma unroll
    for (int p = 0; p < ECHUNKS; p++) {
        s0 += g_part[p * L + t];
        s1 += g_part[p * L + t + 1024];
    }
    float m = warp_max(fmaxf(s0, s1));
    if ((t & 31) == 0) red[t >> 5] = m;
    __syncthreads();
    if (t < 32) { float v = red[t]; v = warp_max(v); if (t == 0) bval = v; }
    __syncthreads();
    float M = bval;
    float e0 = expf(s0 - M), e1 = expf(s1 - M);
    float s = warp_sum(e0 + e1);
    __syncthreads();
    if ((t & 31) == 0) red[t >> 5] = s;
    __syncthreads();
    if (t < 32) { float v = red[t]; v = warp_sum(v); if (t == 0) bval = v; }
    __syncthreads();
    float inv = 1.0f / bval;
    g_attn[t]        = e0 * inv;
    g_attn[t + 1024] = e1 * inv;
}

// ======== k4: warp-per-row. c[r] = attn · cnn_c[r,:] ========
__global__ __launch_bounds__(256) void k4_context(const float* __restrict__ cnn_c) {
    int r    = (blockIdx.x * blockDim.x + threadIdx.x) >> 5;
    int lane = threadIdx.x & 31;
    if (r >= H) return;
    float acc = warp_sum(wdot2048(cnn_c + (size_t)r * L, g_attn, lane));
    if (lane == 0) g_x[H + r] = acc;
}

// ======== k5: warp-per-row. gx[r] = W_ih[r,:]·x + b_ih[r] ========
__global__ __launch_bounds__(256) void k5_gx(
        const float* __restrict__ W_ih, const float* __restrict__ b_ih) {
    int r    = (blockIdx.x * blockDim.x + threadIdx.x) >> 5;
    int lane = threadIdx.x & 31;
    if (r >= H3) return;
    float acc = warp_sum(wdot2048(W_ih + (size_t)r * HE, g_x, lane));
    if (lane == 0) g_gx[r] = acc + b_ih[r];
}

// ======== k6: gate combine -> h_new; also zero g_sum ========
__global__ __launch_bounds__(1024) void k6_combine(const float* __restrict__ h,
                                                   float* __restrict__ out_hidden) {
    int i = threadIdx.x;
    float r  = sigmoidf(g_gx[i]         + g_gh[i]);
    float z  = sigmoidf(g_gx[H + i]     + g_gh[H + i]);
    float n  = tanhf   (g_gx[2 * H + i] + r * g_gh[2 * H + i]);
    float hn = (1.0f - z) * n + z * h[i];
    g_hnew[i] = hn;
    out_hidden[i] = hn;
    if (i == 0) g_sum = 0.f;
}

// ======== k7: persistent warp-per-row logits + fused exp-sum ========
// h_new held in registers across the whole grid-stride loop.
// Logits here are bounded (|logit| < ~20), so unshifted expf is safe in f32.
#define K7_BLOCKS 1184
__global__ __launch_bounds__(128) void k7_logits(
        const float* __restrict__ W_o, const float* __restrict__ b_o,
        float* __restrict__ logits, int V) {
    __shared__ float swarp[4];
    int lane   = threadIdx.x & 31;
    int warpl  = threadIdx.x >> 5;                       // 0..3
    int warpg  = (blockIdx.x * blockDim.x + threadIdx.x) >> 5;
    int nwarps = (gridDim.x * blockDim.x) >> 5;

    const float4* h4 = reinterpret_cast<const float4*>(g_hnew);
    float4 hreg[8];
    #pragma unroll
    for (int k = 0; k < 8; k++) hreg[k] = h4[lane + 32 * k];

    float esum = 0.f;                                    // lane 0 accumulates
    for (int v = warpg; v < V; v += nwarps) {
        const float4* w4 = reinterpret_cast<const float4*>(W_o + (size_t)v * H);
        float4 wv[8];
        #pragma unroll
        for (int k = 0; k < 8; k++) wv[k] = w4[lane + 32 * k];
        float a0 = 0.f, a1 = 0.f;
        #pragma unroll
        for (int k = 0; k < 8; k += 2) {
            a0 += dot4(wv[k],     hreg[k]);
            a1 += dot4(wv[k + 1], hreg[k + 1]);
        }
        float acc = warp_sum(a0 + a1);
        if (lane == 0) {
            float lg = acc + b_o[v];
            logits[v] = lg;
            esum += expf(lg);
        }
    }
    if (lane == 0) swarp[warpl] = esum;
    __syncthreads();
    if (threadIdx.x == 0) {
        float s = swarp[0] + swarp[1] + swarp[2] + swarp[3];
        atomicAdd(&g_sum, s);
    }
}

// ======== k9: out[v] = logits[v] - log(sum_exp) ========
__global__ __launch_bounds__(256) void k9_norm(float* __restrict__ logits, int V) {
    int v = blockIdx.x * blockDim.x + threadIdx.x;
    float lse = logf(g_sum);
    if (v < V) logits[v] -= lse;
}

// ---------------- launch ----------------
extern "C" void kernel_launch(void* const* d_in, const int* in_sizes, int n_in,
                              void* d_out, int out_size) {
    const int*   y_i   = (const int*)  d_in[0];
    const float* h_i   = (const float*)d_in[1];
    const float* cnn_a = (const float*)d_in[2];
    const float* cnn_c = (const float*)d_in[3];
    const float* emb   = (const float*)d_in[4];
    const float* W_t   = (const float*)d_in[5];
    const float* b_t   = (const float*)d_in[6];
    const float* W_ih  = (const float*)d_in[7];
    const float* W_hh  = (const float*)d_in[8];
    const float* b_ih  = (const float*)d_in[9];
    const float* b_hh  = (const float*)d_in[10];
    const float* W_o   = (const float*)d_in[11];
    const float* b_o   = (const float*)d_in[12];

    const int V = in_sizes[11] / H;           // 50257
    float* out        = (float*)d_out;
    float* out_logits = out;
    float* out_hidden = out + (out_size - H);

    // k1: E + H3 = 4096 warp-rows, 8 warps/block
    k1_dvec_gh<<<(E + H3) / 8, 256>>>(y_i, h_i, emb, W_t, b_t, W_hh, b_hh);
    dim3 g2(L / 256, ECHUNKS);
    k2_scores<<<g2, 256>>>(cnn_a);
    k3_softmax<<<1, 1024>>>();
    k4_context<<<H / 8, 256>>>(cnn_c);
    k5_gx<<<H3 / 8, 256>>>(W_ih, b_ih);
    k6_combine<<<1, H>>>(h_i, out_hidden);
    k7_logits<<<K7_BLOCKS, 128>>>(W_o, b_o, out_logits, V);
    k9_norm<<<(V + 255) / 256, 256>>>(out_logits, V);
}

// round 4
// speedup vs baseline: 1.1320x; 1.1320x over previous
#include <cuda_runtime.h>
#include <math.h>

#define H 1024
#define E 1024
#define L 2048
#define HE 2048
#define H3 3072
#define NB 296                   // 2 blocks per SM on 148 SMs (co-resident)
#define TPB 256
#define NTHREADS (NB * TPB)      // 75776
#define NWARPS (NTHREADS / 32)   // 2368

// ---------------- scratch (__device__ globals; no allocation) ----------------
__device__ __align__(16) float g_d[E];
__device__ __align__(16) float g_x[HE];              // [g ; c]
__device__ __align__(16) float g_part[16 * L];
__device__ __align__(16) float g_attn[L];
__device__ __align__(16) float g_gx[H3];
__device__ __align__(16) float g_gh[H3];
__device__ __align__(16) float g_hnew[H];
__device__ float g_sum;
__device__ unsigned g_bar = 0;   // [epoch:12 | count:20] packed grid barrier

// ---------------- helpers ----------------
__device__ __forceinline__ float warp_sum(float v) {
    #pragma unroll
    for (int o = 16; o; o >>= 1) v += __shfl_down_sync(0xffffffffu, v, o);
    return v;
}
__device__ __forceinline__ float warp_max(float v) {
    #pragma unroll
    for (int o = 16; o; o >>= 1) v = fmaxf(v, __shfl_down_sync(0xffffffffu, v, o));
    return v;
}
__device__ __forceinline__ float dot4(const float4 a, const float4 b) {
    return a.x * b.x + a.y * b.y + a.z * b.z + a.w * b.w;
}
__device__ __forceinline__ float sigmoidf(float x) { return 1.0f / (1.0f + expf(-x)); }

// Grid-wide barrier: single packed atomic word, no reset needed (epoch wraps mod 4096).
__device__ __forceinline__ void grid_bar() {
    __syncthreads();
    if (threadIdx.x == 0) {
        __threadfence();
        unsigned old = atomicAdd(&g_bar, 1u);
        unsigned epoch = old >> 20;
        if ((old & 0xFFFFFu) == NB - 1u) {
            // drain count and bump epoch in ONE atomic (new arrivals preserved)
            atomicAdd(&g_bar, (1u << 20) - (unsigned)NB);
        } else {
            while ((atomicAdd(&g_bar, 0u) >> 20) == epoch) __nanosleep(32);
        }
        __threadfence();
    }
    __syncthreads();
}

// warp-cooperative dot over 1024 floats: 8+8 batched LDG.128
__device__ __forceinline__ float wdot1024(const float* __restrict__ row,
                                          const float* __restrict__ vec, int lane) {
    const float4* r4 = reinterpret_cast<const float4*>(row);
    const float4* v4 = reinterpret_cast<const float4*>(vec);
    float4 w[8], x[8];
    #pragma unroll
    for (int k = 0; k < 8; k++) w[k] = r4[lane + 32 * k];
    #pragma unroll
    for (int k = 0; k < 8; k++) x[k] = v4[lane + 32 * k];
    float a0 = 0.f, a1 = 0.f;
    #pragma unroll
    for (int k = 0; k < 8; k += 2) { a0 += dot4(w[k], x[k]); a1 += dot4(w[k+1], x[k+1]); }
    return a0 + a1;  // caller warp-reduces
}
__device__ __forceinline__ float wdot2048(const float* __restrict__ row,
                                          const float* __restrict__ vec, int lane) {
    return wdot1024(row, vec, lane) + wdot1024(row + 1024, vec + 1024, lane);
}

// ================= the whole decoder in one persistent kernel =================
__global__ __launch_bounds__(TPB, 2) void fused_decoder(
        const int* __restrict__ y, const float* __restrict__ h,
        const float* __restrict__ cnn_a, const float* __restrict__ cnn_c,
        const float* __restrict__ emb,
        const float* __restrict__ W_t, const float* __restrict__ b_t,
        const float* __restrict__ W_ih, const float* __restrict__ W_hh,
        const float* __restrict__ b_ih, const float* __restrict__ b_hh,
        const float* __restrict__ W_o, const float* __restrict__ b_o,
        float* __restrict__ out_logits, float* __restrict__ out_hidden, int V) {
    const int lane = threadIdx.x & 31;
    const int gw   = (blockIdx.x * TPB + threadIdx.x) >> 5;  // global warp id
    const int gt   = blockIdx.x * TPB + threadIdx.x;         // global thread id

    // ---- S1: d[e] = W_t[e,:]·h + b_t[e] + g[e]; x[e] = g[e] ----
    for (int e = gw; e < E; e += NWARPS) {
        float acc = warp_sum(wdot1024(W_t + (size_t)e * H, h, lane));
        if (lane == 0) {
            float g = emb[(size_t)y[0] * H + e];
            g_d[e] = acc + b_t[e] + g;
            g_x[e] = g;
        }
    }
    grid_bar();

    // ---- S2 (parallel): scores partials | gh = W_hh·h + b_hh | gx = W_ih[:, :H]·g + b_ih ----
    for (int t = gw; t < 1024 + H3 + H3; t += NWARPS) {
        if (t < 1024) {
            int p = t >> 6, lw = t & 63;
            int l = lw * 32 + lane;
            const float* __restrict__ col = cnn_a + (size_t)(p * 64) * L + l;
            const float* __restrict__ dd  = g_d + p * 64;
            float a0 = 0.f, a1 = 0.f, a2 = 0.f, a3 = 0.f;
            #pragma unroll
            for (int e = 0; e < 64; e += 4) {
                a0 += dd[e]     * col[(size_t)e * L];
                a1 += dd[e + 1] * col[(size_t)(e + 1) * L];
                a2 += dd[e + 2] * col[(size_t)(e + 2) * L];
                a3 += dd[e + 3] * col[(size_t)(e + 3) * L];
            }
            g_part[p * L + l] = (a0 + a1) + (a2 + a3);
        } else if (t < 1024 + H3) {
            int j = t - 1024;
            float acc = warp_sum(wdot1024(W_hh + (size_t)j * H, h, lane));
            if (lane == 0) g_gh[j] = acc + b_hh[j];
        } else {
            int j = t - 1024 - H3;
            float acc = warp_sum(wdot1024(W_ih + (size_t)j * HE, g_x, lane));
            if (lane == 0) g_gx[j] = acc + b_ih[j];
        }
    }
    grid_bar();

    // ---- S3: softmax over L (block 0 only) ----
    if (blockIdx.x == 0) {
        __shared__ float red[8];
        __shared__ float bval;
        int tt = threadIdx.x;
        float v[8];
        float m = -INFINITY;
        #pragma unroll
        for (int j = 0; j < 8; j++) {
            int l = tt + 256 * j;
            float s = 0.f;
            #pragma unroll
            for (int p = 0; p < 16; p++) s += g_part[p * L + l];
            v[j] = s;
            m = fmaxf(m, s);
        }
        m = warp_max(m);
        if (lane == 0) red[tt >> 5] = m;
        __syncthreads();
        if (tt == 0) {
            float mm = red[0];
            #pragma unroll
            for (int i = 1; i < 8; i++) mm = fmaxf(mm, red[i]);
            bval = mm;
        }
        __syncthreads();
        float M = bval;
        float s = 0.f;
        #pragma unroll
        for (int j = 0; j < 8; j++) { v[j] = expf(v[j] - M); s += v[j]; }
        s = warp_sum(s);
        __syncthreads();
        if (lane == 0) red[tt >> 5] = s;
        __syncthreads();
        if (tt == 0) {
            float ss = 0.f;
            #pragma unroll
            for (int i = 0; i < 8; i++) ss += red[i];
            bval = ss;
        }
        __syncthreads();
        float inv = 1.0f / bval;
        #pragma unroll
        for (int j = 0; j < 8; j++) g_attn[tt + 256 * j] = v[j] * inv;
    }
    grid_bar();

    // ---- S4: c[r] = attn · cnn_c[r,:] ----
    for (int r = gw; r < H; r += NWARPS) {
        float acc = warp_sum(wdot2048(cnn_c + (size_t)r * L, g_attn, lane));
        if (lane == 0) g_x[H + r] = acc;
    }
    grid_bar();

    // ---- S5: gx[r] += W_ih[r, H:]·c ----
    for (int r = gw; r < H3; r += NWARPS) {
        float acc = warp_sum(wdot1024(W_ih + (size_t)r * HE + 1024, g_x + 1024, lane));
        if (lane == 0) g_gx[r] += acc;
    }
    grid_bar();

    // ---- S6: GRU gate combine -> h_new; zero g_sum ----
    if (gt < H) {
        int i = gt;
        float r  = sigmoidf(g_gx[i]         + g_gh[i]);
        float z  = sigmoidf(g_gx[H + i]     + g_gh[H + i]);
        float n  = tanhf   (g_gx[2 * H + i] + r * g_gh[2 * H + i]);
        float hn = (1.0f - z) * n + z * h[i];
        g_hnew[i] = hn;
        out_hidden[i] = hn;
    }
    if (gt == 0) g_sum = 0.f;
    grid_bar();

    // ---- S7: logits = W_o·h_new + b_o (2 rows per warp-task) + fused exp-sum ----
    {
        const float4* h4 = reinterpret_cast<const float4*>(g_hnew);
        float4 hreg[8];
        #pragma unroll
        for (int k = 0; k < 8; k++) hreg[k] = h4[lane + 32 * k];
        float esum = 0.f;
        const int ntasks = (V + 1) >> 1;
        for (int t = gw; t < ntasks; t += NWARPS) {
            int v0 = t << 1;
            bool has2 = (v0 + 1 < V);
            const float4* w4 = reinterpret_cast<const float4*>(W_o + (size_t)v0 * H);
            float4 a[8], b[8];
            #pragma unroll
            for (int k = 0; k < 8; k++) a[k] = w4[lane + 32 * k];
            if (has2) {
                #pragma unroll
                for (int k = 0; k < 8; k++) b[k] = w4[256 + lane + 32 * k];
            }
            float d0 = 0.f, d1 = 0.f;
            #pragma unroll
            for (int k = 0; k < 8; k++) d0 += dot4(a[k], hreg[k]);
            if (has2) {
                #pragma unroll
                for (int k = 0; k < 8; k++) d1 += dot4(b[k], hreg[k]);
            }
            d0 = warp_sum(d0);
            d1 = warp_sum(d1);
            if (lane == 0) {
                float lg0 = d0 + b_o[v0];
                out_logits[v0] = lg0;
                esum += expf(lg0);
                if (has2) {
                    float lg1 = d1 + b_o[v0 + 1];
                    out_logits[v0 + 1] = lg1;
                    esum += expf(lg1);
                }
            }
        }
        if (lane == 0) atomicAdd(&g_sum, esum);
    }
    grid_bar();

    // ---- S8: out[v] -= log(sum_exp) ----
    {
        float lse = logf(g_sum);
        for (int v = gt; v < V; v += NTHREADS) out_logits[v] -= lse;
    }
}

// ---------------- launch ----------------
extern "C" void kernel_launch(void* const* d_in, const int* in_sizes, int n_in,
                              void* d_out, int out_size) {
    const int*   y_i   = (const int*)  d_in[0];
    const float* h_i   = (const float*)d_in[1];
    const float* cnn_a = (const float*)d_in[2];
    const float* cnn_c = (const float*)d_in[3];
    const float* emb   = (const float*)d_in[4];
    const float* W_t   = (const float*)d_in[5];
    const float* b_t   = (const float*)d_in[6];
    const float* W_ih  = (const float*)d_in[7];
    const float* W_hh  = (const float*)d_in[8];
    const float* b_ih  = (const float*)d_in[9];
    const float* b_hh  = (const float*)d_in[10];
    const float* W_o   = (const float*)d_in[11];
    const float* b_o   = (const float*)d_in[12];

    const int V = in_sizes[11] / H;           // 50257
    float* out        = (float*)d_out;
    float* out_logits = out;
    float* out_hidden = out + (out_size - H);

    fused_decoder<<<NB, TPB>>>(y_i, h_i, cnn_a, cnn_c, emb, W_t, b_t,
                               W_ih, W_hh, b_ih, b_hh, W_o, b_o,
                               out_logits, out_hidden, V);
}